// round 16
// baseline (speedup 1.0000x reference)
#include <cuda_runtime.h>
#include <math.h>
#include <stdint.h>

// Problem constants
#define DD 256
#define PP 64
#define TINV 10.0f

// Output offsets (floats): routing(65536) | routes(67108864) | tw(65536) | ps(4194304)
#define OFF_ROUTING 0LL
#define OFF_ROUTES  65536LL
#define OFF_TW      67174400LL
#define OFF_PS      67239936LL

#define GRID_TOTAL 2048     // uniform CTAs: 32-row GEMM tile + 1/2048 of all fills

// smem (floats):
//  [0,64) sNorm | [64,128) sInv | [128,384) tmp partials
//  [384, 384+2*32*68)   sA double buffer (raw fp32)
//  [4736, 4736+2*64*68) sB double buffer (raw fp32)
// epilogue overlay: sS[32][66] (2112) fits in sA buffer 0 (2176)
#define PITCH 68
#define ABUF_A (32 * PITCH)                // 2176 floats per A stage
#define ABUF_B (64 * PITCH)                // 4352 floats per B stage
#define SA_OFF 384
#define SB_OFF (SA_OFF + 2 * ABUF_A)       // 4736
#define SMEM_FLOATS (SB_OFF + 2 * ABUF_B)  // 13440
#define SMEM_BYTES (SMEM_FLOATS * 4)       // 53760 B -> 4 CTAs/SM (smem)

// ---- tf32 / async helpers ----
__device__ __forceinline__ unsigned f2tf(float x) {
    unsigned r;
    asm("cvt.rna.tf32.f32 %0, %1;" : "=r"(r) : "f"(x));
    return r;
}
__device__ __forceinline__ void split_tf32(float x, unsigned& hi, unsigned& lo) {
    hi = f2tf(x);
    lo = f2tf(x - __uint_as_float(hi));
}
__device__ __forceinline__ void mma_tf32(float* c,
                                         unsigned a0, unsigned a1, unsigned a2, unsigned a3,
                                         unsigned b0, unsigned b1) {
    asm volatile(
        "mma.sync.aligned.m16n8k8.row.col.f32.tf32.tf32.f32 "
        "{%0,%1,%2,%3}, {%4,%5,%6,%7}, {%8,%9}, {%0,%1,%2,%3};"
        : "+f"(c[0]), "+f"(c[1]), "+f"(c[2]), "+f"(c[3])
        : "r"(a0), "r"(a1), "r"(a2), "r"(a3), "r"(b0), "r"(b1));
}
__device__ __forceinline__ unsigned su32(const void* p) {
    return (unsigned)__cvta_generic_to_shared(p);
}
#define CP16(dst, src) asm volatile("cp.async.cg.shared.global [%0], [%1], 16;" :: "r"(dst), "l"(src))
#define CP_COMMIT()    asm volatile("cp.async.commit_group;" ::: "memory")
#define CP_WAIT1()     asm volatile("cp.async.wait_group 1;" ::: "memory")
#define CP_WAIT0()     asm volatile("cp.async.wait_group 0;" ::: "memory")

// ---------------------------------------------------------------------------
// Uniform fused kernel, 32-row quantum: GEMM+softmax tile + fill share per CTA.
// cp.async double-buffered staging; route stores split across the load-wait
// window and the mma loop for a continuous DRAM write stream.
// ---------------------------------------------------------------------------
__global__ __launch_bounds__(256, 4)
void fused_kernel(const float* __restrict__ states,
                  const float* __restrict__ patterns,
                  const float* __restrict__ tw_in,
                  float* __restrict__ out) {
    extern __shared__ float smem[];
    int bid = blockIdx.x;
    int tid = threadIdx.x;

    long long rowBase = (long long)bid * 32;
    const float* A = states + rowBase * DD;

    float* sNorm = smem;            // [64]
    float* sInv  = smem + 64;       // [32] (64 reserved)
    float* sTmp  = smem + 128;      // [256]
    float* sA    = smem + SA_OFF;   // [2][32][68]
    float* sB    = smem + SB_OFF;   // [2][64][68]

    // ---- hoisted route-fill value (column == 4*tid for all our stores) ----
    float4 rv;
    {
        const float r = 1.0f / 1024.0f;
        int c = tid << 2;
        rv.x = -(float)(c + 0) * r;
        rv.y = -(float)(c + 1) * r;
        rv.z = -(float)(c + 2) * r;
        rv.w = -(float)(c + 3) * r;
    }
    // 8192 float4 per CTA (multiple of 256 -> column invariance holds)
    float4* routes4 = (float4*)(out + OFF_ROUTES) + (long long)bid * 8192 + tid;

    // ---- small fills first: 8 float4 routing + 8 float4 tw per CTA ----
    if (tid < 8) {
        const float r = 1.0f / 1024.0f;
        ((float4*)(out + OFF_ROUTING))[bid * 8 + tid] = make_float4(r, r, r, r);
    } else if (tid < 16) {
        int i4 = bid * 8 + (tid - 8);
        ((float4*)(out + OFF_TW))[i4] = ((const float4*)tw_in)[i4];
    }

    // ---- cp.async staging addresses (2 A-segs + 4 B-segs per thread) ----
    int srow = tid >> 4;           // base row
    int sseg = tid & 15;           // 16B segment within 64-float row
    const float* aSrc = A + (long long)srow * DD + sseg * 4;
    const float* bSrc = patterns + srow * DD + sseg * 4;
    unsigned aDst = su32(sA + srow * PITCH + sseg * 4);
    unsigned bDst = su32(sB + srow * PITCH + sseg * 4);
    const int rstep = 16 * DD;             // 16 rows in gmem
    const unsigned sstep = 16 * PITCH * 4; // 16 rows in smem (bytes)

    // prologue: issue chunk 0 into buffer 0 (A: rows srow, srow+16; B: 4 blocks)
    #pragma unroll
    for (int j = 0; j < 2; j++) CP16(aDst + j * sstep, aSrc + j * rstep);
    #pragma unroll
    for (int j = 0; j < 4; j++) CP16(bDst + j * sstep, bSrc + j * rstep);
    CP_COMMIT();

    // ---- pattern norm partials while chunk 0 is in flight ----
    {
        int p = tid >> 2, q = tid & 3;
        const float4* pv = (const float4*)(patterns + p * DD + q * 64);
        float ss = 0.0f;
        #pragma unroll
        for (int i = 0; i < 16; i++) {
            float4 v = pv[i];
            ss = fmaf(v.x, v.x, fmaf(v.y, v.y, fmaf(v.z, v.z, fmaf(v.w, v.w, ss))));
        }
        sTmp[tid] = ss;
    }

    int w    = tid >> 5;     // warp 0..7
    int lane = tid & 31;
    int g    = lane >> 2;    // group id 0..7
    int tig  = lane & 3;     // thread in group
    int wr   = w & 1;        // row-block (rows wr*16 .. +15)
    int wc   = w >> 1;       // col-quarter (cols wc*16 .. +15)

    float acc[2][4];
    #pragma unroll
    for (int nb = 0; nb < 2; nb++)
        #pragma unroll
        for (int i = 0; i < 4; i++) acc[nb][i] = 0.0f;

    for (int c = 0; c < 4; c++) {       // 4 chunks of K=64
        if (c < 3) {
            unsigned aOff = ((c + 1) & 1) * ABUF_A * 4;
            unsigned bOff = ((c + 1) & 1) * ABUF_B * 4;
            int koff = (c + 1) * 64;
            #pragma unroll
            for (int j = 0; j < 2; j++) CP16(aDst + aOff + j * sstep, aSrc + koff + j * rstep);
            #pragma unroll
            for (int j = 0; j < 4; j++) CP16(bDst + bOff + j * sstep, bSrc + koff + j * rstep);
            CP_COMMIT();
        }

        // route-fill stores in the load-wait window (4 of 8 this chunk)
        #pragma unroll
        for (int j = 0; j < 4; j++)
            __stcs(routes4 + (c * 8 + j) * 256, rv);

        if (c < 3) CP_WAIT1(); else CP_WAIT0();
        __syncthreads();

        if (c == 0 && tid < 64) {
            float s = sTmp[tid * 4] + sTmp[tid * 4 + 1] + sTmp[tid * 4 + 2] + sTmp[tid * 4 + 3];
            sNorm[tid] = 1.0f / fmaxf(sqrtf(s), 1e-12f);
        }

        const float* aRow0 = sA + (c & 1) * ABUF_A + (wr * 16 + g) * PITCH;
        const float* aRow8 = aRow0 + 8 * PITCH;
        const float* bBase = sB + (c & 1) * ABUF_B;
        #pragma unroll
        for (int ks = 0; ks < 8; ks++) {
            int k0 = ks * 8;
            // every other ks: one route store keeps the write stream alive
            if ((ks & 1) == 0)
                __stcs(routes4 + (c * 8 + 4 + (ks >> 1)) * 256, rv);
            unsigned ah0, ah1, ah2, ah3, al0, al1, al2, al3;
            split_tf32(aRow0[k0 + tig],     ah0, al0);
            split_tf32(aRow8[k0 + tig],     ah1, al1);
            split_tf32(aRow0[k0 + tig + 4], ah2, al2);
            split_tf32(aRow8[k0 + tig + 4], ah3, al3);
            #pragma unroll
            for (int nb = 0; nb < 2; nb++) {
                const float* bp = bBase + (wc * 16 + nb * 8 + g) * PITCH + k0 + tig;
                unsigned bh0, bl0, bh1, bl1;
                split_tf32(bp[0], bh0, bl0);
                split_tf32(bp[4], bh1, bl1);
                mma_tf32(acc[nb], ah0, ah1, ah2, ah3, bh0, bh1);
                mma_tf32(acc[nb], ah0, ah1, ah2, ah3, bl0, bl1);
                mma_tf32(acc[nb], al0, al1, al2, al3, bh0, bh1);
            }
        }
        __syncthreads();
    }

    // ================ epilogue: scale by pattern norms, softmax per row ================
    float* sS = sA;   // overlay [32][66] in buffer 0
    {
        int r0 = wr * 16 + g;
        #pragma unroll
        for (int nb = 0; nb < 2; nb++) {
            int col = wc * 16 + nb * 8 + 2 * tig;
            float inv0 = sNorm[col], inv1 = sNorm[col + 1];
            *(float2*)&sS[r0 * 66 + col]       = make_float2(acc[nb][0] * inv0, acc[nb][1] * inv1);
            *(float2*)&sS[(r0 + 8) * 66 + col] = make_float2(acc[nb][2] * inv0, acc[nb][3] * inv1);
        }
    }
    __syncthreads();

    // 8 threads per row: thread (row, q) handles 8 patterns; shfl-combine.
    {
        int row = tid >> 3;
        int q   = tid & 7;
        float* rowp = &sS[row * 66 + q * 8];
        float mx = -1e30f;
        #pragma unroll
        for (int p = 0; p < 8; p++) mx = fmaxf(mx, rowp[p]);
        mx = fmaxf(mx, __shfl_xor_sync(0xFFFFFFFFu, mx, 1));
        mx = fmaxf(mx, __shfl_xor_sync(0xFFFFFFFFu, mx, 2));
        mx = fmaxf(mx, __shfl_xor_sync(0xFFFFFFFFu, mx, 4));
        mx *= TINV;
        float sum = 0.0f;
        #pragma unroll
        for (int p = 0; p < 8; p++) {
            float e = __expf(rowp[p] * TINV - mx);
            rowp[p] = e;
            sum += e;
        }
        sum += __shfl_xor_sync(0xFFFFFFFFu, sum, 1);
        sum += __shfl_xor_sync(0xFFFFFFFFu, sum, 2);
        sum += __shfl_xor_sync(0xFFFFFFFFu, sum, 4);
        if (q == 0) sInv[row] = 1.0f / sum;
    }
    __syncthreads();

    // coalesced streaming store of the 32x64 tile (512 float4, 2 per thread)
    float* O = out + OFF_PS + rowBase * PP;
    #pragma unroll
    for (int j = 0; j < 2; j++) {
        int i = tid + j * 256;
        int row = i >> 4, pq = (i & 15) << 2;
        float inv = sInv[row];
        float4 v = make_float4(sS[row * 66 + pq + 0] * inv,
                               sS[row * 66 + pq + 1] * inv,
                               sS[row * 66 + pq + 2] * inv,
                               sS[row * 66 + pq + 3] * inv);
        __stcs((float4*)&O[row * PP + pq], v);
    }
}

extern "C" void kernel_launch(void* const* d_in, const int* in_sizes, int n_in,
                              void* d_out, int out_size) {
    const float* states   = (const float*)d_in[0];  // (4,16,1024,256)
    const float* patterns = (const float*)d_in[1];  // (64,256)
    const float* tw       = (const float*)d_in[2];  // (16,64,64)
    float* out = (float*)d_out;

    cudaFuncSetAttribute(fused_kernel,
                         cudaFuncAttributeMaxDynamicSharedMemorySize,
                         SMEM_BYTES);

    fused_kernel<<<GRID_TOTAL, 256, SMEM_BYTES>>>(states, patterns, tw, out);
}

// round 17
// speedup vs baseline: 1.2252x; 1.2252x over previous
#include <cuda_runtime.h>
#include <math.h>
#include <stdint.h>

// Problem constants
#define DD 256
#define PP 64
#define TINV 10.0f

// Output offsets (floats): routing(65536) | routes(67108864) | tw(65536) | ps(4194304)
#define OFF_ROUTING 0LL
#define OFF_ROUTES  65536LL
#define OFF_TW      67174400LL
#define OFF_PS      67239936LL

#define GRID_TOTAL 1024     // uniform CTAs: 64-row GEMM tile + 1/1024 of all fills

// smem (floats):
//  [0,64) sNorm | [64,128) sInv | [128,384) tmp partials
//  [384, 384+2*64*68)  sA double buffer (raw fp32)
//  [9088, 9088+2*64*68) sB double buffer (raw fp32)
// epilogue overlay: sS[64][66] (4224) fits in sA buffer 0 (4352)
#define PITCH 68
#define ABUF (64 * PITCH)                  // 4352 floats per stage
#define SA_OFF 384
#define SB_OFF (SA_OFF + 2 * ABUF)         // 9088
#define SMEM_FLOATS (SB_OFF + 2 * ABUF)    // 17792
#define SMEM_BYTES (SMEM_FLOATS * 4)       // 71168 B -> 3 CTAs/SM

// ---- tf32 / async helpers ----
__device__ __forceinline__ unsigned f2tf(float x) {
    unsigned r;
    asm("cvt.rna.tf32.f32 %0, %1;" : "=r"(r) : "f"(x));
    return r;
}
__device__ __forceinline__ void split_tf32(float x, unsigned& hi, unsigned& lo) {
    hi = f2tf(x);
    lo = f2tf(x - __uint_as_float(hi));
}
__device__ __forceinline__ void mma_tf32(float* c,
                                         unsigned a0, unsigned a1, unsigned a2, unsigned a3,
                                         unsigned b0, unsigned b1) {
    asm volatile(
        "mma.sync.aligned.m16n8k8.row.col.f32.tf32.tf32.f32 "
        "{%0,%1,%2,%3}, {%4,%5,%6,%7}, {%8,%9}, {%0,%1,%2,%3};"
        : "+f"(c[0]), "+f"(c[1]), "+f"(c[2]), "+f"(c[3])
        : "r"(a0), "r"(a1), "r"(a2), "r"(a3), "r"(b0), "r"(b1));
}
__device__ __forceinline__ unsigned su32(const void* p) {
    return (unsigned)__cvta_generic_to_shared(p);
}
#define CP16(dst, src) asm volatile("cp.async.cg.shared.global [%0], [%1], 16;" :: "r"(dst), "l"(src))
#define CP_COMMIT()    asm volatile("cp.async.commit_group;" ::: "memory")
#define CP_WAIT1()     asm volatile("cp.async.wait_group 1;" ::: "memory")
#define CP_WAIT0()     asm volatile("cp.async.wait_group 0;" ::: "memory")

// ---------------------------------------------------------------------------
// Uniform fused kernel: 64-row GEMM+softmax tile + fill share per CTA.
// cp.async double-buffered staging. Route stores: 8 in the load-wait window,
// 8 interleaved into the mma loop -> continuous DRAM write stream per CTA.
// ---------------------------------------------------------------------------
__global__ __launch_bounds__(256, 3)
void fused_kernel(const float* __restrict__ states,
                  const float* __restrict__ patterns,
                  const float* __restrict__ tw_in,
                  float* __restrict__ out) {
    extern __shared__ float smem[];
    int bid = blockIdx.x;
    int tid = threadIdx.x;

    long long rowBase = (long long)bid * 64;
    const float* A = states + rowBase * DD;

    float* sNorm = smem;            // [64]
    float* sInv  = smem + 64;       // [64]
    float* sTmp  = smem + 128;      // [256]
    float* sA    = smem + SA_OFF;   // [2][64][68]
    float* sB    = smem + SB_OFF;   // [2][64][68]

    // ---- hoisted route-fill value (column == 4*tid for all our stores) ----
    float4 rv;
    {
        const float r = 1.0f / 1024.0f;
        int c = tid << 2;
        rv.x = -(float)(c + 0) * r;
        rv.y = -(float)(c + 1) * r;
        rv.z = -(float)(c + 2) * r;
        rv.w = -(float)(c + 3) * r;
    }
    float4* routes4 = (float4*)(out + OFF_ROUTES) + (long long)bid * 16384 + tid;

    // ---- small fills first: pure stores, fully independent of everything ----
    if (tid < 16) {
        const float r = 1.0f / 1024.0f;
        ((float4*)(out + OFF_ROUTING))[bid * 16 + tid] = make_float4(r, r, r, r);
    } else if (tid < 32) {
        int i4 = bid * 16 + (tid - 16);
        ((float4*)(out + OFF_TW))[i4] = ((const float4*)tw_in)[i4];
    }

    // ---- cp.async staging addresses (4 A-segs + 4 B-segs per thread) ----
    int srow = tid >> 4;           // base row (rows srow, srow+16, srow+32, srow+48)
    int sseg = tid & 15;           // 16B segment within 64-float row
    const float* aSrc = A + (long long)srow * DD + sseg * 4;
    const float* bSrc = patterns + srow * DD + sseg * 4;
    unsigned aDst = su32(sA + srow * PITCH + sseg * 4);
    unsigned bDst = su32(sB + srow * PITCH + sseg * 4);
    const int rstep = 16 * DD;             // 16 rows in gmem
    const unsigned sstep = 16 * PITCH * 4; // 16 rows in smem (bytes)

    // prologue: issue chunk 0 into buffer 0
    #pragma unroll
    for (int j = 0; j < 4; j++) {
        CP16(aDst + j * sstep, aSrc + j * rstep);
        CP16(bDst + j * sstep, bSrc + j * rstep);
    }
    CP_COMMIT();

    // ---- pattern norm partials while chunk 0 is in flight ----
    {
        int p = tid >> 2, q = tid & 3;
        const float4* pv = (const float4*)(patterns + p * DD + q * 64);
        float ss = 0.0f;
        #pragma unroll
        for (int i = 0; i < 16; i++) {
            float4 v = pv[i];
            ss = fmaf(v.x, v.x, fmaf(v.y, v.y, fmaf(v.z, v.z, fmaf(v.w, v.w, ss))));
        }
        sTmp[tid] = ss;
    }

    int w    = tid >> 5;     // warp 0..7
    int lane = tid & 31;
    int g    = lane >> 2;    // group id 0..7
    int tig  = lane & 3;     // thread in group
    int wr   = w & 3;        // row-block (rows wr*16 .. +15)
    int wc   = w >> 2;       // col-half  (cols wc*32 .. +31)

    float acc[4][4];
    #pragma unroll
    for (int nb = 0; nb < 4; nb++)
        #pragma unroll
        for (int i = 0; i < 4; i++) acc[nb][i] = 0.0f;

    for (int c = 0; c < 4; c++) {       // 4 chunks of K=64
        if (c < 3) {
            unsigned boff = ((c + 1) & 1) * ABUF * 4;
            int koff = (c + 1) * 64;
            #pragma unroll
            for (int j = 0; j < 4; j++) {
                CP16(aDst + boff + j * sstep, aSrc + koff + j * rstep);
                CP16(bDst + boff + j * sstep, bSrc + koff + j * rstep);
            }
            CP_COMMIT();
        }

        // route-fill stores in the load-wait window (8 of 16 this chunk)
        #pragma unroll
        for (int j = 0; j < 8; j++)
            __stcs(routes4 + (c * 16 + j) * 256, rv);

        if (c < 3) CP_WAIT1(); else CP_WAIT0();
        __syncthreads();

        if (c == 0 && tid < 64) {
            float s = sTmp[tid * 4] + sTmp[tid * 4 + 1] + sTmp[tid * 4 + 2] + sTmp[tid * 4 + 3];
            sNorm[tid] = 1.0f / fmaxf(sqrtf(s), 1e-12f);
        }

        const float* aRow0 = sA + (c & 1) * ABUF + (wr * 16 + g) * PITCH;
        const float* aRow8 = aRow0 + 8 * PITCH;
        const float* bBase = sB + (c & 1) * ABUF;
        #pragma unroll
        for (int ks = 0; ks < 8; ks++) {
            int k0 = ks * 8;
            // one route store per ks: keeps write stream alive through mma phase
            __stcs(routes4 + (c * 16 + 8 + ks) * 256, rv);
            unsigned ah0, ah1, ah2, ah3, al0, al1, al2, al3;
            split_tf32(aRow0[k0 + tig],     ah0, al0);
            split_tf32(aRow8[k0 + tig],     ah1, al1);
            split_tf32(aRow0[k0 + tig + 4], ah2, al2);
            split_tf32(aRow8[k0 + tig + 4], ah3, al3);
            #pragma unroll
            for (int nb = 0; nb < 4; nb++) {
                const float* bp = bBase + (wc * 32 + nb * 8 + g) * PITCH + k0 + tig;
                unsigned bh0, bl0, bh1, bl1;
                split_tf32(bp[0], bh0, bl0);
                split_tf32(bp[4], bh1, bl1);
                mma_tf32(acc[nb], ah0, ah1, ah2, ah3, bh0, bh1);
                mma_tf32(acc[nb], ah0, ah1, ah2, ah3, bl0, bl1);
                mma_tf32(acc[nb], al0, al1, al2, al3, bh0, bh1);
            }
        }
        __syncthreads();
    }

    // ================ epilogue: scale by pattern norms, softmax per row ================
    float* sS = sA;   // overlay [64][66] in buffer 0
    {
        int r0 = wr * 16 + g;
        #pragma unroll
        for (int nb = 0; nb < 4; nb++) {
            int col = wc * 32 + nb * 8 + 2 * tig;
            float inv0 = sNorm[col], inv1 = sNorm[col + 1];
            *(float2*)&sS[r0 * 66 + col]       = make_float2(acc[nb][0] * inv0, acc[nb][1] * inv1);
            *(float2*)&sS[(r0 + 8) * 66 + col] = make_float2(acc[nb][2] * inv0, acc[nb][3] * inv1);
        }
    }
    __syncthreads();

    // 4 threads per row: thread (row, q) handles 16 patterns; shfl-combine.
    {
        int row = tid >> 2;
        int q   = tid & 3;
        float* rowp = &sS[row * 66 + q * 16];
        float mx = -1e30f;
        #pragma unroll
        for (int p = 0; p < 16; p++) mx = fmaxf(mx, rowp[p]);
        mx = fmaxf(mx, __shfl_xor_sync(0xFFFFFFFFu, mx, 1));
        mx = fmaxf(mx, __shfl_xor_sync(0xFFFFFFFFu, mx, 2));
        mx *= TINV;
        float sum = 0.0f;
        #pragma unroll
        for (int p = 0; p < 16; p++) {
            float e = __expf(rowp[p] * TINV - mx);
            rowp[p] = e;
            sum += e;
        }
        sum += __shfl_xor_sync(0xFFFFFFFFu, sum, 1);
        sum += __shfl_xor_sync(0xFFFFFFFFu, sum, 2);
        if (q == 0) sInv[row] = 1.0f / sum;
    }
    __syncthreads();

    // coalesced streaming store of the 64x64 tile
    float* O = out + OFF_PS + rowBase * PP;
    #pragma unroll
    for (int j = 0; j < 4; j++) {
        int i = tid + j * 256;
        int row = i >> 4, pq = (i & 15) << 2;
        float inv = sInv[row];
        float4 v = make_float4(sS[row * 66 + pq + 0] * inv,
                               sS[row * 66 + pq + 1] * inv,
                               sS[row * 66 + pq + 2] * inv,
                               sS[row * 66 + pq + 3] * inv);
        __stcs((float4*)&O[row * PP + pq], v);
    }
}

extern "C" void kernel_launch(void* const* d_in, const int* in_sizes, int n_in,
                              void* d_out, int out_size) {
    const float* states   = (const float*)d_in[0];  // (4,16,1024,256)
    const float* patterns = (const float*)d_in[1];  // (64,256)
    const float* tw       = (const float*)d_in[2];  // (16,64,64)
    float* out = (float*)d_out;

    cudaFuncSetAttribute(fused_kernel,
                         cudaFuncAttributeMaxDynamicSharedMemorySize,
                         SMEM_BYTES);

    fused_kernel<<<GRID_TOTAL, 256, SMEM_BYTES>>>(states, patterns, tw, out);
}